// round 11
// baseline (speedup 1.0000x reference)
#include <cuda_runtime.h>

#define Nn 50000
#define Ee 500000
#define NTILES 3907        // ceil(E/128)
#define NODE_TILES 1563    // ceil(N/32)

typedef unsigned long long u64;

// ---------------- device scratch (no cudaMalloc allowed) --------------------
__device__ __align__(16) float g_UP [(size_t)Nn * 256]; // {up0, up1x, up1y, up1z}
__device__ __align__(16) float g_MSG[(size_t)Nn * 256]; // {m0,  m1x,  m1y,  m1z }
__device__ __align__(16) float g_stats[192];
__device__ __align__(16) float g_norm[192];

__device__ __forceinline__ float silu_f(float x) {
    return __fdividef(x, 1.f + __expf(-x));
}

// ---- packed f32x2 helpers (sm_100+) ----------------------------------------
__device__ __forceinline__ u64 bcast2(float x) {
    u64 r; asm("mov.b64 %0, {%1, %1};" : "=l"(r) : "f"(x)); return r;
}
__device__ __forceinline__ void fma2(u64 &d, u64 a, u64 b) {
    asm("fma.rn.f32x2 %0, %1, %2, %0;" : "+l"(d) : "l"(a), "l"(b));
}
__device__ __forceinline__ float2 unpack2(u64 v) {
    float x, y; asm("mov.b64 {%0, %1}, %2;" : "=f"(x), "=f"(y) : "l"(v));
    return make_float2(x, y);
}
__device__ __forceinline__ u64 d2u(double d) { return __double_as_longlong(d); }

// ============================================================================
__global__ void k_zero() {
    size_t i = (size_t)blockIdx.x * blockDim.x + threadIdx.x;
    float4 z = make_float4(0.f, 0.f, 0.f, 0.f);
    if (i < (size_t)Nn * 64) ((float4*)g_MSG)[i] = z;
    if (i < 48) ((float4*)g_stats)[i] = z;
}

// ============================================================================
// k_up: 64 nodes/block. UP[n][d] = {h0@Wup0, (h1@Wup1).xyz}
// ============================================================================
__global__ __launch_bounds__(256, 1)
void k_up(const float* __restrict__ h, const float* __restrict__ W0,
          const float* __restrict__ W1)
{
    extern __shared__ float sm[];
    float* sW0 = sm;
    float* sW1 = sm + 4096;
    float* hT  = sm + 8192;           // [(comp*64+c)*68 + n]
    const int tid = threadIdx.x;
    for (int i = tid; i < 4096; i += 256) { sW0[i] = W0[i]; sW1[i] = W1[i]; }
    const int nbase = blockIdx.x * 64;
    for (int i = tid; i < 64 * 256; i += 256) {
        int n = i >> 8, col = i & 255;
        int nn = nbase + n;
        float v = (nn < Nn) ? h[(size_t)nn * 256 + col] : 0.f;
        int comp, c;
        if (col < 64) { comp = 0; c = col; }
        else          { comp = 1 + (col - 64) % 3; c = (col - 64) / 3; }
        hT[(comp * 64 + c) * 68 + n] = v;
    }
    __syncthreads();
    const int dg = tid & 15, ng = tid >> 4;
    for (int pass = 0; pass < 2; ++pass) {
        int n0 = pass * 32 + ng * 2;
        float acc[4][4][2];
#pragma unroll
        for (int q = 0; q < 4; q++)
#pragma unroll
            for (int a = 0; a < 4; a++) { acc[q][a][0] = 0.f; acc[q][a][1] = 0.f; }
#pragma unroll 8
        for (int c = 0; c < 64; c++) {
            float4 w0 = *(const float4*)&sW0[c * 64 + dg * 4];
            float4 w1 = *(const float4*)&sW1[c * 64 + dg * 4];
            float w0v[4] = {w0.x, w0.y, w0.z, w0.w};
            float w1v[4] = {w1.x, w1.y, w1.z, w1.w};
            float hv[4][2];
#pragma unroll
            for (int q = 0; q < 4; q++) {
                hv[q][0] = hT[(q * 64 + c) * 68 + n0];
                hv[q][1] = hT[(q * 64 + c) * 68 + n0 + 1];
            }
#pragma unroll
            for (int a = 0; a < 4; a++)
#pragma unroll
                for (int nn = 0; nn < 2; nn++) {
                    acc[0][a][nn] = fmaf(hv[0][nn], w0v[a], acc[0][a][nn]);
                    acc[1][a][nn] = fmaf(hv[1][nn], w1v[a], acc[1][a][nn]);
                    acc[2][a][nn] = fmaf(hv[2][nn], w1v[a], acc[2][a][nn]);
                    acc[3][a][nn] = fmaf(hv[3][nn], w1v[a], acc[3][a][nn]);
                }
        }
#pragma unroll
        for (int a = 0; a < 4; a++)
#pragma unroll
            for (int nn = 0; nn < 2; nn++) {
                int n = nbase + n0 + nn;
                if (n < Nn)
                    *(float4*)&g_UP[((size_t)n * 64 + dg * 4 + a) * 4] =
                        make_float4(acc[0][a][nn], acc[1][a][nn],
                                    acc[2][a][nn], acc[3][a][nn]);
            }
    }
}

// ============================================================================
// k_edge with packed f32x2 math.
// Smem layout (floats):
//   sM1   @     0 (1024)   sM2 @ 1024 (4096)   sM3 @ 5120 (4096)
//   sM4   @  9216 (16384)  re-laid: [(j*64+c)*4 + k]
//   rbfT  @ 25600 (16x260, DUP)   bufA @ 29760 (64x260, DUP)
//   bufB  @ 46400 (64x132, plain)
//   sSnd  @ 54848 (128 int)  sRcv @ 54976 (128 int)  sSh @ 55104 (128 float4)
//   total 55616 floats = 222464 B
// ============================================================================

// channel-paired stage: dup input (broadcast b64 free), W pairs free via double2
template<int K, bool OUTDUP>
__device__ __forceinline__ void mlp_stage_cp(const float* __restrict__ W,
                                             const float* __restrict__ inD,
                                             float* __restrict__ outT,
                                             int dg, int eg4)
{
    u64 acc[2][4];
#pragma unroll
    for (int cp = 0; cp < 2; cp++)
#pragma unroll
        for (int e = 0; e < 4; e++) acc[cp][e] = 0ull;
#pragma unroll 4
    for (int j = 0; j < K; j++) {
        double2 wd = *(const double2*)(W + j * 64 + dg * 4);
        const double2* rp = (const double2*)(inD + j * 260 + eg4 * 8);
        double2 r01 = rp[0], r23 = rp[1];
        u64 w0 = d2u(wd.x), w1 = d2u(wd.y);
        u64 rb[4] = { d2u(r01.x), d2u(r01.y), d2u(r23.x), d2u(r23.y) };
#pragma unroll
        for (int e = 0; e < 4; e++) {
            fma2(acc[0][e], w0, rb[e]);
            fma2(acc[1][e], w1, rb[e]);
        }
    }
    float v[4][4];
#pragma unroll
    for (int cp = 0; cp < 2; cp++)
#pragma unroll
        for (int e = 0; e < 4; e++) {
            float2 t = unpack2(acc[cp][e]);
            v[2 * cp][e]     = silu_f(t.x);
            v[2 * cp + 1][e] = silu_f(t.y);
        }
#pragma unroll
    for (int a = 0; a < 4; a++) {
        if (OUTDUP) {
            float* o = outT + (dg * 4 + a) * 260 + eg4 * 8;
            *(float4*)o       = make_float4(v[a][0], v[a][0], v[a][1], v[a][1]);
            *(float4*)(o + 4) = make_float4(v[a][2], v[a][2], v[a][3], v[a][3]);
        } else {
            *(float4*)(outT + (dg * 4 + a) * 132 + eg4 * 4) =
                make_float4(v[a][0], v[a][1], v[a][2], v[a][3]);
        }
    }
}

// edge-paired stage: plain input (edge pairs free), W broadcast via MOV packs
__device__ __forceinline__ void mlp_stage_ep(const float* __restrict__ W,
                                             const float* __restrict__ inP,
                                             float* __restrict__ outD,
                                             int dg, int eg4)
{
    u64 acc[4][2];
#pragma unroll
    for (int a = 0; a < 4; a++) { acc[a][0] = 0ull; acc[a][1] = 0ull; }
#pragma unroll 4
    for (int j = 0; j < 64; j++) {
        float4 w = *(const float4*)(W + j * 64 + dg * 4);
        double2 rd = *(const double2*)(inP + j * 132 + eg4 * 4);
        u64 r0 = d2u(rd.x), r1 = d2u(rd.y);
        u64 wb[4] = { bcast2(w.x), bcast2(w.y), bcast2(w.z), bcast2(w.w) };
#pragma unroll
        for (int a = 0; a < 4; a++) {
            fma2(acc[a][0], wb[a], r0);
            fma2(acc[a][1], wb[a], r1);
        }
    }
#pragma unroll
    for (int a = 0; a < 4; a++) {
        float2 p0 = unpack2(acc[a][0]), p1 = unpack2(acc[a][1]);
        float s0 = silu_f(p0.x), s1 = silu_f(p0.y);
        float s2 = silu_f(p1.x), s3 = silu_f(p1.y);
        float* o = outD + (dg * 4 + a) * 260 + eg4 * 8;
        *(float4*)o       = make_float4(s0, s0, s1, s1);
        *(float4*)(o + 4) = make_float4(s2, s2, s3, s3);
    }
}

__global__ __launch_bounds__(512, 1)
void k_edge(const float* __restrict__ rbf, const int* __restrict__ ei,
            const float* __restrict__ sh,
            const float* __restrict__ M1, const float* __restrict__ M2,
            const float* __restrict__ M3, const float* __restrict__ M4)
{
    extern __shared__ float sm[];
    float*  sM1  = sm;                    // 1024
    float*  sM2  = sm + 1024;             // 4096
    float*  sM3  = sm + 5120;             // 4096
    float*  sM4  = sm + 9216;             // 16384, [(j*64+c)*4 + k]
    float*  rbfT = sm + 25600;            // 16 x 260 (dup)
    float*  bufA = sm + 29760;            // 64 x 260 (dup)
    float*  bufB = sm + 46400;            // 64 x 132 (plain)
    int*    sSnd = (int*)  (sm + 54848);  // 128
    int*    sRcv = (int*)  (sm + 54976);  // 128
    float4* sSh  = (float4*)(sm + 55104); // 128 x float4
    const int tid = threadIdx.x;
    for (int i = tid; i < 1024; i += 512) sM1[i] = M1[i];
    for (int i = tid; i < 4096; i += 512) { sM2[i] = M2[i]; sM3[i] = M3[i]; }
    for (int i = tid; i < 16384; i += 512) {
        int j = i >> 8, rem = i & 255, c = rem >> 2, k = rem & 3;
        sM4[i] = M4[j * 256 + k * 64 + c];
    }

    const int dg = tid & 15, eg4 = tid >> 4;   // stages 1-3
    const int cc = tid & 63, eg8 = tid >> 6;   // stage 4
    const float inv3 = 0.57735026918962576f;

    for (int tile = blockIdx.x; tile < NTILES; tile += gridDim.x) {
        const int ebase = tile * 128;
        for (int i = tid; i < 2048; i += 512) {
            int el = i >> 4, j = i & 15;
            int e = ebase + el;
            float v = (e < Ee) ? rbf[(size_t)e * 16 + j] : 0.f;
            rbfT[j * 260 + 2 * el]     = v;
            rbfT[j * 260 + 2 * el + 1] = v;
        }
        for (int i = tid; i < 128; i += 512) {
            int e = ebase + i;
            if (e < Ee) {
                sSnd[i] = ei[e]; sRcv[i] = ei[Ee + e];
                sSh[i] = *(const float4*)&sh[(size_t)e * 4];
            } else {
                sSnd[i] = 0; sRcv[i] = 0;
                sSh[i] = make_float4(0.f, 0.f, 0.f, 0.f);
            }
        }
        __syncthreads();
        mlp_stage_cp<16, true >(sM1, rbfT, bufA, dg, eg4);   // rbf -> A (dup)
        __syncthreads();
        mlp_stage_cp<64, false>(sM2, bufA, bufB, dg, eg4);   // A -> B (plain)
        __syncthreads();
        mlp_stage_ep(sM3, bufB, bufA, dg, eg4);              // B -> A (dup)
        __syncthreads();
        // stage 4 (no silu) fused with message formation + scatter
#pragma unroll 1
        for (int pass = 0; pass < 2; ++pass) {
            const int elo = pass * 64 + eg8 * 8;
            u64 t01[8], t23[8];
#pragma unroll
            for (int i = 0; i < 8; i++) { t01[i] = 0ull; t23[i] = 0ull; }
#pragma unroll 4
            for (int j = 0; j < 64; j++) {
                double2 wd = *(const double2*)(sM4 + (j * 64 + cc) * 4);
                u64 w01 = d2u(wd.x), w23 = d2u(wd.y);
                const double2* rp = (const double2*)(bufA + j * 260 + 2 * elo);
                double2 ra = rp[0], rb = rp[1], rc2 = rp[2], rd2 = rp[3];
                u64 rr[8] = { d2u(ra.x),  d2u(ra.y),  d2u(rb.x),  d2u(rb.y),
                              d2u(rc2.x), d2u(rc2.y), d2u(rd2.x), d2u(rd2.y) };
#pragma unroll
                for (int i = 0; i < 8; i++) {
                    fma2(t01[i], w01, rr[i]);
                    fma2(t23[i], w23, rr[i]);
                }
            }
            float t0[8], t1[8], t2[8], t3[8];
#pragma unroll
            for (int i = 0; i < 8; i++) {
                float2 p = unpack2(t01[i]); t0[i] = p.x; t1[i] = p.y;
                float2 q = unpack2(t23[i]); t2[i] = q.x; t3[i] = q.y;
            }
#pragma unroll 1
            for (int g = 0; g < 2; ++g) {
                float4 u[4], s4[4]; int rc[4], vd[4];
#pragma unroll
                for (int i = 0; i < 4; i++) {
                    int li = elo + g * 4 + i;
                    vd[i] = (ebase + li) < Ee;
                    int snd = sSnd[li];
                    rc[i] = sRcv[li];
                    s4[i] = sSh[li];
                    u[i] = *(const float4*)&g_UP[((size_t)snd * 64 + cc) * 4];
                }
#pragma unroll
                for (int i = 0; i < 4; i++) {
                    if (!vd[i]) continue;
                    int k = g * 4 + i;
                    float dot = u[i].y * s4[i].y + u[i].z * s4[i].z + u[i].w * s4[i].w;
                    float m0 = t0[k] * u[i].x * s4[i].x + t3[k] * dot * inv3;
                    float mx = t1[k] * u[i].x * s4[i].y + t2[k] * u[i].y * s4[i].x;
                    float my = t1[k] * u[i].x * s4[i].z + t2[k] * u[i].z * s4[i].x;
                    float mz = t1[k] * u[i].x * s4[i].w + t2[k] * u[i].w * s4[i].x;
                    float* p = &g_MSG[((size_t)rc[i] * 64 + cc) * 4];
                    asm volatile("red.global.add.v4.f32 [%0], {%1,%2,%3,%4};"
                                 :: "l"(__cvta_generic_to_global(p)),
                                    "f"(m0), "f"(mx), "f"(my), "f"(mz) : "memory");
                }
            }
        }
        __syncthreads();   // protect smem before next tile
    }
}

// ============================================================================
// k_node: persistent, 32 nodes/tile, 512 threads (1 node/thread).
// ============================================================================
__global__ __launch_bounds__(512, 1)
void k_node(const float* __restrict__ h,
            const float* __restrict__ Wl0, const float* __restrict__ Wl1,
            const float* __restrict__ Ws0, const float* __restrict__ Ws1,
            const float* __restrict__ Wc0, const float* __restrict__ Wc1,
            const float* __restrict__ WB0, const float* __restrict__ WB1,
            float* __restrict__ out)
{
    extern __shared__ float sm[];
    float* sWl0 = sm;
    float* sWl1 = sm + 4096;
    float* sWs0 = sm + 8192;
    float* sWs1 = sm + 12288;
    float* sWB0 = sm + 16384;
    float* sWB1 = sm + 20480;
    float* sWc0 = sm + 24576;            // 320
    float* sWc1 = sm + 24896;            // 256
    float* buf1 = sm + 25152;            // [4][64][36]
    float* buf2 = sm + 34368;            // [4][64][36]
    float* sStat = sm + 43584;           // 192
    const int tid = threadIdx.x;
    for (int i = tid; i < 4096; i += 512) {
        sWl0[i] = Wl0[i]; sWl1[i] = Wl1[i];
        sWs0[i] = Ws0[i]; sWs1[i] = Ws1[i];
        sWB0[i] = WB0[i]; sWB1[i] = WB1[i];
    }
    for (int i = tid; i < 320; i += 512) sWc0[i] = Wc0[i];
    if (tid < 256) sWc1[tid] = Wc1[tid];
    if (tid < 192) sStat[tid] = 0.f;
    const int dg = tid & 15, ng = tid >> 4;   // ng in [0,32): one node/thread

    for (int tile = blockIdx.x; tile < NODE_TILES; tile += gridDim.x) {
        const int nbase = tile * 32;
        __syncthreads();                         // init + prev-tile buf reads
        for (int i = tid; i < 2048; i += 512) {  // MSG -> buf1 (transposed)
            int c = i & 63, n = i >> 6;
            int nn = nbase + n;
            float4 v = make_float4(0.f, 0.f, 0.f, 0.f);
            if (nn < Nn) v = *(const float4*)&g_MSG[((size_t)nn * 64 + c) * 4];
            buf1[(c)       * 36 + n] = v.x;
            buf1[(64 + c)  * 36 + n] = v.y;
            buf1[(128 + c) * 36 + n] = v.z;
            buf1[(192 + c) * 36 + n] = v.w;
        }
        __syncthreads();
#pragma unroll 1
        for (int q = 0; q < 4; ++q) {            // A = msg @ Wlin
            const float* W  = q ? sWl1 : sWl0;
            const float* in = buf1 + q * 2304;
            float* ob = buf2 + q * 2304;
            float acc[4];
#pragma unroll
            for (int a = 0; a < 4; a++) acc[a] = 0.f;
#pragma unroll 8
            for (int c = 0; c < 64; c++) {
                float4 w = *(const float4*)&W[c * 64 + dg * 4];
                float i0 = in[c * 36 + ng];
                acc[0] = fmaf(i0, w.x, acc[0]);
                acc[1] = fmaf(i0, w.y, acc[1]);
                acc[2] = fmaf(i0, w.z, acc[2]);
                acc[3] = fmaf(i0, w.w, acc[3]);
            }
#pragma unroll
            for (int a = 0; a < 4; a++)
                ob[(dg * 4 + a) * 36 + ng] = acc[a];
        }
        __syncthreads();
        for (int i = tid; i < 8192; i += 512) {  // h -> buf1 (transposed)
            int n = i >> 8, col = i & 255;
            int nn = nbase + n;
            float v = (nn < Nn) ? h[(size_t)nn * 256 + col] : 0.f;
            int q, c;
            if (col < 64) { q = 0; c = col; }
            else          { q = 1 + (col - 64) % 3; c = (col - 64) / 3; }
            buf1[(q * 64 + c) * 36 + n] = v;
        }
        for (int i = tid; i < 2048; i += 512) {  // polynomial on buf2 in place
            int c = i >> 5, n = i & 31;
            float A0 = buf2[c * 36 + n];
            float Ax = buf2[(64 + c)  * 36 + n];
            float Ay = buf2[(128 + c) * 36 + n];
            float Az = buf2[(192 + c) * 36 + n];
            float vv = Ax * Ax + Ay * Ay + Az * Az;
            float A2 = A0 * A0;
            const float* w5 = &sWc0[c * 5];
            const float* w4 = &sWc1[c * 4];
            float B0 = w5[0] * A0 + w5[1] * A2 + w5[2] * vv
                     + w5[3] * A2 * A0 + w5[4] * A0 * vv;
            float f = w4[0] + w4[1] * A0 + w4[2] * A2 + w4[3] * vv;
            buf2[c * 36 + n]         = B0;
            buf2[(64 + c)  * 36 + n] = f * Ax;
            buf2[(128 + c) * 36 + n] = f * Ay;
            buf2[(192 + c) * 36 + n] = f * Az;
        }
        __syncthreads();
        float o[4][4];                           // o = B@WB + h@Wsc (1 node)
#pragma unroll
        for (int q = 0; q < 4; q++)
#pragma unroll
            for (int a = 0; a < 4; a++) o[q][a] = 0.f;
#pragma unroll 4
        for (int c = 0; c < 64; c++) {
            float4 b0 = *(const float4*)&sWB0[c * 64 + dg * 4];
            float4 b1 = *(const float4*)&sWB1[c * 64 + dg * 4];
            float4 s0 = *(const float4*)&sWs0[c * 64 + dg * 4];
            float4 s1 = *(const float4*)&sWs1[c * 64 + dg * 4];
            float wB[2][4] = {{b0.x, b0.y, b0.z, b0.w}, {b1.x, b1.y, b1.z, b1.w}};
            float wS[2][4] = {{s0.x, s0.y, s0.z, s0.w}, {s1.x, s1.y, s1.z, s1.w}};
#pragma unroll
            for (int q = 0; q < 4; q++) {
                int s = q ? 1 : 0;
                float bv = buf2[q * 2304 + c * 36 + ng];
                float hv = buf1[q * 2304 + c * 36 + ng];
#pragma unroll
                for (int a = 0; a < 4; a++)
                    o[q][a] = fmaf(bv, wB[s][a], fmaf(hv, wS[s][a], o[q][a]));
            }
        }
        {
            int n = nbase + ng;
            if (n < Nn) {
#pragma unroll
                for (int a = 0; a < 4; a++) {
                    int d = dg * 4 + a;
                    out[(size_t)n * 256 + d]              = o[0][a];
                    out[(size_t)n * 256 + 64 + d * 3]     = o[1][a];
                    out[(size_t)n * 256 + 64 + d * 3 + 1] = o[2][a];
                    out[(size_t)n * 256 + 64 + d * 3 + 2] = o[3][a];
                }
            }
        }
#pragma unroll
        for (int a = 0; a < 4; a++) {
            int d = dg * 4 + a;
            float v0 = o[0][a];
            float s1s = o[1][a] * o[1][a] + o[2][a] * o[2][a] + o[3][a] * o[3][a];
            atomicAdd(&sStat[d], v0);
            atomicAdd(&sStat[64 + d], v0 * v0);
            atomicAdd(&sStat[128 + d], s1s);
        }
    }
    __syncthreads();
    if (tid < 192) atomicAdd(&g_stats[tid], sStat[tid]);
}

// ============================================================================
__global__ void k_finalize(const float* __restrict__ gamma0,
                           const float* __restrict__ beta0,
                           const float* __restrict__ gamma1)
{
    int c = threadIdx.x;
    if (c >= 64) return;
    const float invN = 1.f / (float)Nn;
    float mu  = g_stats[c] * invN;
    float var = fmaxf(g_stats[64 + c] * invN - mu * mu, 0.f);
    float a   = rsqrtf(var + 1e-5f) * gamma0[c];
    g_norm[c]        = a;
    g_norm[64 + c]   = beta0[c] - mu * a;
    g_norm[128 + c]  = rsqrtf(g_stats[128 + c] * invN * (1.f / 3.f) + 1e-5f) * gamma1[c];
}

__global__ void k_norm(float* __restrict__ out)
{
    size_t i = (size_t)blockIdx.x * blockDim.x + threadIdx.x;
    if (i >= (size_t)Nn * 64) return;
    float4 v = ((float4*)out)[i];
    int col = ((int)(i & 63)) * 4;
    float r[4] = {v.x, v.y, v.z, v.w};
#pragma unroll
    for (int k = 0; k < 4; k++) {
        int cl = col + k;
        if (cl < 64) r[k] = r[k] * g_norm[cl] + g_norm[64 + cl];
        else         r[k] = r[k] * g_norm[128 + (cl - 64) / 3];
    }
    ((float4*)out)[i] = make_float4(r[0], r[1], r[2], r[3]);
}

// ============================================================================
extern "C" void kernel_launch(void* const* d_in, const int* in_sizes, int n_in,
                              void* d_out, int out_size)
{
    const float* h    = (const float*)d_in[0];
    const int*   ei   = (const int*)  d_in[1];
    const float* sh   = (const float*)d_in[2];
    const float* rbf  = (const float*)d_in[3];
    const float* Wup0 = (const float*)d_in[4];
    const float* Wup1 = (const float*)d_in[5];
    const float* M1   = (const float*)d_in[6];
    const float* M2   = (const float*)d_in[7];
    const float* M3   = (const float*)d_in[8];
    const float* M4   = (const float*)d_in[9];
    const float* Wl0  = (const float*)d_in[10];
    const float* Wl1  = (const float*)d_in[11];
    const float* Ws0  = (const float*)d_in[12];
    const float* Ws1  = (const float*)d_in[13];
    const float* Wc0  = (const float*)d_in[14];
    const float* Wc1  = (const float*)d_in[15];
    const float* WB0  = (const float*)d_in[16];
    const float* WB1  = (const float*)d_in[17];
    const float* g0   = (const float*)d_in[18];
    const float* b0   = (const float*)d_in[19];
    const float* g1   = (const float*)d_in[20];
    float* out = (float*)d_out;

    cudaFuncSetAttribute(k_up,   cudaFuncAttributeMaxDynamicSharedMemorySize, 102400);
    cudaFuncSetAttribute(k_edge, cudaFuncAttributeMaxDynamicSharedMemorySize, 222464);
    cudaFuncSetAttribute(k_node, cudaFuncAttributeMaxDynamicSharedMemorySize, 175104);

    k_zero<<<12500, 256>>>();
    k_up<<<782, 256, 102400>>>(h, Wup0, Wup1);
    k_edge<<<152, 512, 222464>>>(rbf, ei, sh, M1, M2, M3, M4);
    k_node<<<152, 512, 175104>>>(h, Wl0, Wl1, Ws0, Ws1, Wc0, Wc1, WB0, WB1, out);
    k_finalize<<<1, 64>>>(g0, b0, g1);
    k_norm<<<12500, 256>>>(out);
}

// round 13
// speedup vs baseline: 1.1344x; 1.1344x over previous
#include <cuda_runtime.h>

#define Nn 50000
#define Ee 500000
#define NTILES 3907        // ceil(E/128)
#define NODE_TILES 1563    // ceil(N/32)

// ---------------- device scratch (no cudaMalloc allowed) --------------------
__device__ __align__(16) float g_UP [(size_t)Nn * 256]; // {up0, up1x, up1y, up1z}
__device__ __align__(16) float g_MSG[(size_t)Nn * 256]; // {m0,  m1x,  m1y,  m1z }
__device__ __align__(16) float g_stats[192];
__device__ __align__(16) float g_norm[192];

__device__ __forceinline__ float silu_f(float x) {
    return __fdividef(x, 1.f + __expf(-x));
}

// ============================================================================
__global__ void k_zero() {
    size_t i = (size_t)blockIdx.x * blockDim.x + threadIdx.x;
    float4 z = make_float4(0.f, 0.f, 0.f, 0.f);
    if (i < (size_t)Nn * 64) ((float4*)g_MSG)[i] = z;
    if (i < 48) ((float4*)g_stats)[i] = z;
}

// ============================================================================
// k_up: 64 nodes/block. UP[n][d] = {h0@Wup0, (h1@Wup1).xyz}
// ============================================================================
__global__ __launch_bounds__(256, 1)
void k_up(const float* __restrict__ h, const float* __restrict__ W0,
          const float* __restrict__ W1)
{
    extern __shared__ float sm[];
    float* sW0 = sm;
    float* sW1 = sm + 4096;
    float* hT  = sm + 8192;           // [(comp*64+c)*68 + n]
    const int tid = threadIdx.x;
    for (int i = tid; i < 4096; i += 256) { sW0[i] = W0[i]; sW1[i] = W1[i]; }
    const int nbase = blockIdx.x * 64;
    for (int i = tid; i < 64 * 256; i += 256) {
        int n = i >> 8, col = i & 255;
        int nn = nbase + n;
        float v = (nn < Nn) ? h[(size_t)nn * 256 + col] : 0.f;
        int comp, c;
        if (col < 64) { comp = 0; c = col; }
        else          { comp = 1 + (col - 64) % 3; c = (col - 64) / 3; }
        hT[(comp * 64 + c) * 68 + n] = v;
    }
    __syncthreads();
    const int dg = tid & 15, ng = tid >> 4;
    for (int pass = 0; pass < 2; ++pass) {
        int n0 = pass * 32 + ng * 2;
        float acc[4][4][2];
#pragma unroll
        for (int q = 0; q < 4; q++)
#pragma unroll
            for (int a = 0; a < 4; a++) { acc[q][a][0] = 0.f; acc[q][a][1] = 0.f; }
#pragma unroll 8
        for (int c = 0; c < 64; c++) {
            float4 w0 = *(const float4*)&sW0[c * 64 + dg * 4];
            float4 w1 = *(const float4*)&sW1[c * 64 + dg * 4];
            float w0v[4] = {w0.x, w0.y, w0.z, w0.w};
            float w1v[4] = {w1.x, w1.y, w1.z, w1.w};
            float hv[4][2];
#pragma unroll
            for (int q = 0; q < 4; q++) {
                hv[q][0] = hT[(q * 64 + c) * 68 + n0];
                hv[q][1] = hT[(q * 64 + c) * 68 + n0 + 1];
            }
#pragma unroll
            for (int a = 0; a < 4; a++)
#pragma unroll
                for (int nn = 0; nn < 2; nn++) {
                    acc[0][a][nn] = fmaf(hv[0][nn], w0v[a], acc[0][a][nn]);
                    acc[1][a][nn] = fmaf(hv[1][nn], w1v[a], acc[1][a][nn]);
                    acc[2][a][nn] = fmaf(hv[2][nn], w1v[a], acc[2][a][nn]);
                    acc[3][a][nn] = fmaf(hv[3][nn], w1v[a], acc[3][a][nn]);
                }
        }
#pragma unroll
        for (int a = 0; a < 4; a++)
#pragma unroll
            for (int nn = 0; nn < 2; nn++) {
                int n = nbase + n0 + nn;
                if (n < Nn)
                    *(float4*)&g_UP[((size_t)n * 64 + dg * 4 + a) * 4] =
                        make_float4(acc[0][a][nn], acc[1][a][nn],
                                    acc[2][a][nn], acc[3][a][nn]);
            }
    }
}

// ============================================================================
// k_edge: persistent (R8 form — measured ~860us, near scalar FMA floor).
// ============================================================================
template <int K>
__device__ __forceinline__ void mlp_stage(const float* __restrict__ W,
                                          const float* __restrict__ inT,
                                          float* __restrict__ outT,
                                          int dg, int eg4)
{
    float acc[4][4];
#pragma unroll
    for (int a = 0; a < 4; a++)
#pragma unroll
        for (int b = 0; b < 4; b++) acc[a][b] = 0.f;
#pragma unroll 8
    for (int j = 0; j < K; j++) {
        float4 w = *(const float4*)(W + j * 64 + dg * 4);
        float4 r = *(const float4*)(inT + j * 132 + eg4 * 4);
        float wv[4] = {w.x, w.y, w.z, w.w};
        float rv[4] = {r.x, r.y, r.z, r.w};
#pragma unroll
        for (int a = 0; a < 4; a++)
#pragma unroll
            for (int b = 0; b < 4; b++)
                acc[a][b] = fmaf(wv[a], rv[b], acc[a][b]);
    }
#pragma unroll
    for (int a = 0; a < 4; a++) {
        float4 o;
        o.x = silu_f(acc[a][0]); o.y = silu_f(acc[a][1]);
        o.z = silu_f(acc[a][2]); o.w = silu_f(acc[a][3]);
        *(float4*)(outT + (dg * 4 + a) * 132 + eg4 * 4) = o;
    }
}

__global__ __launch_bounds__(512, 1)
void k_edge(const float* __restrict__ rbf, const int* __restrict__ ei,
            const float* __restrict__ sh,
            const float* __restrict__ M1, const float* __restrict__ M2,
            const float* __restrict__ M3, const float* __restrict__ M4)
{
    extern __shared__ float sm[];
    float*  sM1  = sm;                   // 1024
    float*  sM2  = sm + 1024;            // 4096
    float*  sM3  = sm + 5120;            // 4096
    float*  sM4  = sm + 9216;            // 16384
    float*  rbfT = sm + 25600;           // 16 x 132
    float*  bufA = sm + 27712;           // 64 x 132
    float*  bufB = sm + 36160;           // 64 x 132
    int*    sSnd = (int*)  (sm + 44608); // 128
    int*    sRcv = (int*)  (sm + 44736); // 128
    float4* sSh  = (float4*)(sm + 44864);// 128 x float4
    const int tid = threadIdx.x;
    for (int i = tid; i < 1024; i += 512) sM1[i] = M1[i];
    for (int i = tid; i < 4096; i += 512) { sM2[i] = M2[i]; sM3[i] = M3[i]; }
    for (int i = tid; i < 16384; i += 512) sM4[i] = M4[i];

    const int dg = tid & 15, eg4 = tid >> 4;   // stages 1-3
    const int cc = tid & 63, eg8 = tid >> 6;   // stage 4
    const float inv3 = 0.57735026918962576f;

    for (int tile = blockIdx.x; tile < NTILES; tile += gridDim.x) {
        const int ebase = tile * 128;
        for (int i = tid; i < 2048; i += 512) {
            int el = i >> 4, j = i & 15;
            int e = ebase + el;
            rbfT[j * 132 + el] = (e < Ee) ? rbf[(size_t)e * 16 + j] : 0.f;
        }
        for (int i = tid; i < 128; i += 512) {
            int e = ebase + i;
            if (e < Ee) {
                sSnd[i] = ei[e]; sRcv[i] = ei[Ee + e];
                sSh[i] = *(const float4*)&sh[(size_t)e * 4];
            } else {
                sSnd[i] = 0; sRcv[i] = 0;
                sSh[i] = make_float4(0.f, 0.f, 0.f, 0.f);
            }
        }
        __syncthreads();
        mlp_stage<16>(sM1, rbfT, bufA, dg, eg4);
        __syncthreads();
        mlp_stage<64>(sM2, bufA, bufB, dg, eg4);
        __syncthreads();
        mlp_stage<64>(sM3, bufB, bufA, dg, eg4);
        __syncthreads();
        // stage 4 (no silu) fused with message formation + scatter
#pragma unroll 1
        for (int pass = 0; pass < 2; ++pass) {
            const int elo = pass * 64 + eg8 * 8;
            float t0[8], t1[8], t2[8], t3[8];
#pragma unroll
            for (int i = 0; i < 8; i++) { t0[i] = 0.f; t1[i] = 0.f; t2[i] = 0.f; t3[i] = 0.f; }
#pragma unroll 4
            for (int j = 0; j < 64; j++) {
                const float* m4p = &sM4[j * 256 + cc];
                float w0 = m4p[0], w1 = m4p[64], w2 = m4p[128], w3 = m4p[192];
                const float* rp = &bufA[j * 132 + elo];
                float4 ra = *(const float4*)rp;
                float4 rb = *(const float4*)(rp + 4);
                float rr[8] = {ra.x, ra.y, ra.z, ra.w, rb.x, rb.y, rb.z, rb.w};
#pragma unroll
                for (int i = 0; i < 8; i++) {
                    t0[i] = fmaf(rr[i], w0, t0[i]);
                    t1[i] = fmaf(rr[i], w1, t1[i]);
                    t2[i] = fmaf(rr[i], w2, t2[i]);
                    t3[i] = fmaf(rr[i], w3, t3[i]);
                }
            }
#pragma unroll 1
            for (int g = 0; g < 2; ++g) {
                float4 u[4], s4[4]; int rc[4], vd[4];
#pragma unroll
                for (int i = 0; i < 4; i++) {
                    int li = elo + g * 4 + i;
                    vd[i] = (ebase + li) < Ee;
                    int snd = sSnd[li];
                    rc[i] = sRcv[li];
                    s4[i] = sSh[li];
                    u[i] = *(const float4*)&g_UP[((size_t)snd * 64 + cc) * 4];
                }
#pragma unroll
                for (int i = 0; i < 4; i++) {
                    if (!vd[i]) continue;
                    int k = g * 4 + i;
                    float dot = u[i].y * s4[i].y + u[i].z * s4[i].z + u[i].w * s4[i].w;
                    float m0 = t0[k] * u[i].x * s4[i].x + t3[k] * dot * inv3;
                    float mx = t1[k] * u[i].x * s4[i].y + t2[k] * u[i].y * s4[i].x;
                    float my = t1[k] * u[i].x * s4[i].z + t2[k] * u[i].z * s4[i].x;
                    float mz = t1[k] * u[i].x * s4[i].w + t2[k] * u[i].w * s4[i].x;
                    float* p = &g_MSG[((size_t)rc[i] * 64 + cc) * 4];
                    asm volatile("red.global.add.v4.f32 [%0], {%1,%2,%3,%4};"
                                 :: "l"(__cvta_generic_to_global(p)),
                                    "f"(m0), "f"(mx), "f"(my), "f"(mz) : "memory");
                }
            }
        }
        __syncthreads();   // protect sSnd/sRcv/sSh + bufA before next tile
    }
}

// ============================================================================
// k_node: persistent, 32 nodes/tile, 256 threads, 2 nodes/thread (R8 config)
// + fused q=1..3 A-GEMV sharing one Wl1 load (halves A-phase weight LDS).
// ============================================================================
__global__ __launch_bounds__(256, 1)
void k_node(const float* __restrict__ h,
            const float* __restrict__ Wl0, const float* __restrict__ Wl1,
            const float* __restrict__ Ws0, const float* __restrict__ Ws1,
            const float* __restrict__ Wc0, const float* __restrict__ Wc1,
            const float* __restrict__ WB0, const float* __restrict__ WB1,
            float* __restrict__ out)
{
    extern __shared__ float sm[];
    float* sWl0 = sm;
    float* sWl1 = sm + 4096;
    float* sWs0 = sm + 8192;
    float* sWs1 = sm + 12288;
    float* sWB0 = sm + 16384;
    float* sWB1 = sm + 20480;
    float* sWc0 = sm + 24576;            // 320
    float* sWc1 = sm + 24896;            // 256
    float* buf1 = sm + 25152;            // [4][64][36]
    float* buf2 = sm + 34368;            // [4][64][36]
    float* sStat = sm + 43584;           // 192
    const int tid = threadIdx.x;
    for (int i = tid; i < 4096; i += 256) {
        sWl0[i] = Wl0[i]; sWl1[i] = Wl1[i];
        sWs0[i] = Ws0[i]; sWs1[i] = Ws1[i];
        sWB0[i] = WB0[i]; sWB1[i] = WB1[i];
    }
    for (int i = tid; i < 320; i += 256) sWc0[i] = Wc0[i];
    if (tid < 256) sWc1[tid] = Wc1[tid];
    if (tid < 192) sStat[tid] = 0.f;
    const int dg = tid & 15, ng = tid >> 4, nb = ng * 2;

    for (int tile = blockIdx.x; tile < NODE_TILES; tile += gridDim.x) {
        const int nbase = tile * 32;
        __syncthreads();                         // init + prev-tile buf reads
        for (int i = tid; i < 2048; i += 256) {  // MSG -> buf1 (transposed)
            int c = i & 63, n = i >> 6;
            int nn = nbase + n;
            float4 v = make_float4(0.f, 0.f, 0.f, 0.f);
            if (nn < Nn) v = *(const float4*)&g_MSG[((size_t)nn * 64 + c) * 4];
            buf1[(c)       * 36 + n] = v.x;
            buf1[(64 + c)  * 36 + n] = v.y;
            buf1[(128 + c) * 36 + n] = v.z;
            buf1[(192 + c) * 36 + n] = v.w;
        }
        __syncthreads();
        // ---- A-GEMV, q = 0 (Wl0) ----
        {
            float acc[4][2];
#pragma unroll
            for (int a = 0; a < 4; a++) { acc[a][0] = 0.f; acc[a][1] = 0.f; }
#pragma unroll 8
            for (int c = 0; c < 64; c++) {
                float4 w = *(const float4*)&sWl0[c * 64 + dg * 4];
                float wv[4] = {w.x, w.y, w.z, w.w};
                float i0 = buf1[c * 36 + nb], i1 = buf1[c * 36 + nb + 1];
#pragma unroll
                for (int a = 0; a < 4; a++) {
                    acc[a][0] = fmaf(i0, wv[a], acc[a][0]);
                    acc[a][1] = fmaf(i1, wv[a], acc[a][1]);
                }
            }
#pragma unroll
            for (int a = 0; a < 4; a++) {
                buf2[(dg * 4 + a) * 36 + nb]     = acc[a][0];
                buf2[(dg * 4 + a) * 36 + nb + 1] = acc[a][1];
            }
        }
        // ---- A-GEMV, q = 1..3 fused (one shared Wl1 load per c) ----
        {
            float acc[3][4][2];
#pragma unroll
            for (int p = 0; p < 3; p++)
#pragma unroll
                for (int a = 0; a < 4; a++) { acc[p][a][0] = 0.f; acc[p][a][1] = 0.f; }
#pragma unroll 4
            for (int c = 0; c < 64; c++) {
                float4 w = *(const float4*)&sWl1[c * 64 + dg * 4];
                float wv[4] = {w.x, w.y, w.z, w.w};
#pragma unroll
                for (int p = 0; p < 3; p++) {
                    float i0 = buf1[((1 + p) * 64 + c) * 36 + nb];
                    float i1 = buf1[((1 + p) * 64 + c) * 36 + nb + 1];
#pragma unroll
                    for (int a = 0; a < 4; a++) {
                        acc[p][a][0] = fmaf(i0, wv[a], acc[p][a][0]);
                        acc[p][a][1] = fmaf(i1, wv[a], acc[p][a][1]);
                    }
                }
            }
#pragma unroll
            for (int p = 0; p < 3; p++)
#pragma unroll
                for (int a = 0; a < 4; a++) {
                    buf2[((1 + p) * 64 + dg * 4 + a) * 36 + nb]     = acc[p][a][0];
                    buf2[((1 + p) * 64 + dg * 4 + a) * 36 + nb + 1] = acc[p][a][1];
                }
        }
        __syncthreads();
        for (int i = tid; i < 8192; i += 256) {  // h -> buf1 (transposed)
            int n = i >> 8, col = i & 255;
            int nn = nbase + n;
            float v = (nn < Nn) ? h[(size_t)nn * 256 + col] : 0.f;
            int q, c;
            if (col < 64) { q = 0; c = col; }
            else          { q = 1 + (col - 64) % 3; c = (col - 64) / 3; }
            buf1[(q * 64 + c) * 36 + n] = v;
        }
        for (int i = tid; i < 2048; i += 256) {  // polynomial on buf2 in place
            int c = i >> 5, n = i & 31;
            float A0 = buf2[c * 36 + n];
            float Ax = buf2[(64 + c)  * 36 + n];
            float Ay = buf2[(128 + c) * 36 + n];
            float Az = buf2[(192 + c) * 36 + n];
            float vv = Ax * Ax + Ay * Ay + Az * Az;
            float A2 = A0 * A0;
            const float* w5 = &sWc0[c * 5];
            const float* w4 = &sWc1[c * 4];
            float B0 = w5[0] * A0 + w5[1] * A2 + w5[2] * vv
                     + w5[3] * A2 * A0 + w5[4] * A0 * vv;
            float f = w4[0] + w4[1] * A0 + w4[2] * A2 + w4[3] * vv;
            buf2[c * 36 + n]         = B0;
            buf2[(64 + c)  * 36 + n] = f * Ax;
            buf2[(128 + c) * 36 + n] = f * Ay;
            buf2[(192 + c) * 36 + n] = f * Az;
        }
        __syncthreads();
        float o[4][4][2];                        // o = B@WB + h@Wsc
#pragma unroll
        for (int q = 0; q < 4; q++)
#pragma unroll
            for (int a = 0; a < 4; a++) { o[q][a][0] = 0.f; o[q][a][1] = 0.f; }
#pragma unroll 4
        for (int c = 0; c < 64; c++) {
            float4 b0 = *(const float4*)&sWB0[c * 64 + dg * 4];
            float4 b1 = *(const float4*)&sWB1[c * 64 + dg * 4];
            float4 s0 = *(const float4*)&sWs0[c * 64 + dg * 4];
            float4 s1 = *(const float4*)&sWs1[c * 64 + dg * 4];
            float wB[2][4] = {{b0.x, b0.y, b0.z, b0.w}, {b1.x, b1.y, b1.z, b1.w}};
            float wS[2][4] = {{s0.x, s0.y, s0.z, s0.w}, {s1.x, s1.y, s1.z, s1.w}};
#pragma unroll
            for (int q = 0; q < 4; q++) {
                int s = q ? 1 : 0;
                float bv0 = buf2[q * 2304 + c * 36 + nb];
                float bv1 = buf2[q * 2304 + c * 36 + nb + 1];
                float hv0 = buf1[q * 2304 + c * 36 + nb];
                float hv1 = buf1[q * 2304 + c * 36 + nb + 1];
#pragma unroll
                for (int a = 0; a < 4; a++) {
                    o[q][a][0] = fmaf(bv0, wB[s][a], fmaf(hv0, wS[s][a], o[q][a][0]));
                    o[q][a][1] = fmaf(bv1, wB[s][a], fmaf(hv1, wS[s][a], o[q][a][1]));
                }
            }
        }
#pragma unroll
        for (int nn = 0; nn < 2; nn++) {
            int n = nbase + nb + nn;
            if (n < Nn) {
#pragma unroll
                for (int a = 0; a < 4; a++) {
                    int d = dg * 4 + a;
                    out[(size_t)n * 256 + d]              = o[0][a][nn];
                    out[(size_t)n * 256 + 64 + d * 3]     = o[1][a][nn];
                    out[(size_t)n * 256 + 64 + d * 3 + 1] = o[2][a][nn];
                    out[(size_t)n * 256 + 64 + d * 3 + 2] = o[3][a][nn];
                }
            }
        }
#pragma unroll
        for (int a = 0; a < 4; a++) {
            int d = dg * 4 + a;
            float sv = 0.f, sq = 0.f, s1s = 0.f;
#pragma unroll
            for (int nn = 0; nn < 2; nn++) {
                float v0 = o[0][a][nn];
                sv += v0; sq += v0 * v0;
                s1s += o[1][a][nn] * o[1][a][nn] + o[2][a][nn] * o[2][a][nn]
                     + o[3][a][nn] * o[3][a][nn];
            }
            atomicAdd(&sStat[d], sv);
            atomicAdd(&sStat[64 + d], sq);
            atomicAdd(&sStat[128 + d], s1s);
        }
    }
    __syncthreads();
    if (tid < 192) atomicAdd(&g_stats[tid], sStat[tid]);
}

// ============================================================================
__global__ void k_finalize(const float* __restrict__ gamma0,
                           const float* __restrict__ beta0,
                           const float* __restrict__ gamma1)
{
    int c = threadIdx.x;
    if (c >= 64) return;
    const float invN = 1.f / (float)Nn;
    float mu  = g_stats[c] * invN;
    float var = fmaxf(g_stats[64 + c] * invN - mu * mu, 0.f);
    float a   = rsqrtf(var + 1e-5f) * gamma0[c];
    g_norm[c]        = a;
    g_norm[64 + c]   = beta0[c] - mu * a;
    g_norm[128 + c]  = rsqrtf(g_stats[128 + c] * invN * (1.f / 3.f) + 1e-5f) * gamma1[c];
}

__global__ void k_norm(float* __restrict__ out)
{
    size_t i = (size_t)blockIdx.x * blockDim.x + threadIdx.x;
    if (i >= (size_t)Nn * 64) return;
    float4 v = ((float4*)out)[i];
    int col = ((int)(i & 63)) * 4;
    float r[4] = {v.x, v.y, v.z, v.w};
#pragma unroll
    for (int k = 0; k < 4; k++) {
        int cl = col + k;
        if (cl < 64) r[k] = r[k] * g_norm[cl] + g_norm[64 + cl];
        else         r[k] = r[k] * g_norm[128 + (cl - 64) / 3];
    }
    ((float4*)out)[i] = make_float4(r[0], r[1], r[2], r[3]);
}

// ============================================================================
extern "C" void kernel_launch(void* const* d_in, const int* in_sizes, int n_in,
                              void* d_out, int out_size)
{
    const float* h    = (const float*)d_in[0];
    const int*   ei   = (const int*)  d_in[1];
    const float* sh   = (const float*)d_in[2];
    const float* rbf  = (const float*)d_in[3];
    const float* Wup0 = (const float*)d_in[4];
    const float* Wup1 = (const float*)d_in[5];
    const float* M1   = (const float*)d_in[6];
    const float* M2   = (const float*)d_in[7];
    const float* M3   = (const float*)d_in[8];
    const float* M4   = (const float*)d_in[9];
    const float* Wl0  = (const float*)d_in[10];
    const float* Wl1  = (const float*)d_in[11];
    const float* Ws0  = (const float*)d_in[12];
    const float* Ws1  = (const float*)d_in[13];
    const float* Wc0  = (const float*)d_in[14];
    const float* Wc1  = (const float*)d_in[15];
    const float* WB0  = (const float*)d_in[16];
    const float* WB1  = (const float*)d_in[17];
    const float* g0   = (const float*)d_in[18];
    const float* b0   = (const float*)d_in[19];
    const float* g1   = (const float*)d_in[20];
    float* out = (float*)d_out;

    cudaFuncSetAttribute(k_up,   cudaFuncAttributeMaxDynamicSharedMemorySize, 102400);
    cudaFuncSetAttribute(k_edge, cudaFuncAttributeMaxDynamicSharedMemorySize, 181504);
    cudaFuncSetAttribute(k_node, cudaFuncAttributeMaxDynamicSharedMemorySize, 175104);

    k_zero<<<12500, 256>>>();
    k_up<<<782, 256, 102400>>>(h, Wup0, Wup1);
    k_edge<<<152, 512, 181504>>>(rbf, ei, sh, M1, M2, M3, M4);
    k_node<<<152, 256, 175104>>>(h, Wl0, Wl1, Ws0, Ws1, Wc0, Wc1, WB0, WB1, out);
    k_finalize<<<1, 64>>>(g0, b0, g1);
    k_norm<<<12500, 256>>>(out);
}